// round 1
// baseline (speedup 1.0000x reference)
#include <cuda_runtime.h>
#include <math.h>
#include <float.h>

#define N_NODES 100000
#define N_EDGES 1600000
#define DIM 128
#define NB 128
#define NEG 0.01f

// ---------------- scratch (static device globals; no allocation) ----------------
__device__ float g_agg[N_NODES * DIM];      // aggregated x (then GEMM input)
__device__ float g_dinv[N_NODES];
__device__ int   g_deg[N_NODES];
__device__ int   g_offs[N_NODES + 1];
__device__ int   g_cursor[N_NODES];
__device__ int   g_csr[N_EDGES];            // source node per CSR slot (dest-sorted)
__device__ int   g_bsum[128];               // scan spine (98 blocks)
__device__ float g_pool[2 * NB * DIM];      // segment_max pools, both branches
__device__ float g_gp[2 * NB * DIM];        // after fc_p + lrelu
__device__ float g_c1[NB * 256];
__device__ float g_c2[NB * 64];

__device__ __forceinline__ float lrelu(float v) { return v >= 0.f ? v : NEG * v; }

__device__ __forceinline__ void atomicMaxFloat(float* addr, float v) {
    if (v >= 0.f) atomicMax((int*)addr, __float_as_int(v));
    else          atomicMin((unsigned int*)addr, __float_as_uint(v));
}

// ---------------- degree / scan / CSR build ----------------
__global__ void k_zero_deg() {
    int i = blockIdx.x * blockDim.x + threadIdx.x;
    if (i < N_NODES) g_deg[i] = 0;
}

__global__ void k_count(const int* __restrict__ col) {
    int e = blockIdx.x * blockDim.x + threadIdx.x;
    if (e < N_EDGES) atomicAdd(&g_deg[col[e]], 1);
}

__global__ void k_dinv() {
    int i = blockIdx.x * blockDim.x + threadIdx.x;
    if (i < N_NODES) g_dinv[i] = rsqrtf((float)(g_deg[i] + 1));  // +1 self loop
}

__global__ void k_scan1() {   // grid 98, block 1024: exclusive scan within block
    __shared__ int sh[1024];
    int t = threadIdx.x;
    int i = blockIdx.x * 1024 + t;
    int v = (i < N_NODES) ? g_deg[i] : 0;
    sh[t] = v;
    __syncthreads();
    #pragma unroll
    for (int off = 1; off < 1024; off <<= 1) {
        int x = (t >= off) ? sh[t - off] : 0;
        __syncthreads();
        sh[t] += x;
        __syncthreads();
    }
    if (i < N_NODES) g_offs[i] = sh[t] - v;     // exclusive
    if (t == 1023) g_bsum[blockIdx.x] = sh[t];  // block total
}

__global__ void k_scan2() {   // 1 block, 128 threads: exclusive scan of 98 spine values
    __shared__ int sh[128];
    int t = threadIdx.x;
    int v = (t < 98) ? g_bsum[t] : 0;
    sh[t] = v;
    __syncthreads();
    #pragma unroll
    for (int off = 1; off < 128; off <<= 1) {
        int x = (t >= off) ? sh[t - off] : 0;
        __syncthreads();
        sh[t] += x;
        __syncthreads();
    }
    if (t < 98) g_bsum[t] = sh[t] - v;
}

__global__ void k_scan3() {   // grid 98, block 1024: add spine, init cursor
    int t = threadIdx.x;
    int i = blockIdx.x * 1024 + t;
    if (i < N_NODES) {
        int v = g_offs[i] + g_bsum[blockIdx.x];
        g_offs[i] = v;
        g_cursor[i] = v;
    }
    if (i == 0) g_offs[N_NODES] = N_EDGES;
}

__global__ void k_fill(const int* __restrict__ row, const int* __restrict__ col) {
    int e = blockIdx.x * blockDim.x + threadIdx.x;
    if (e < N_EDGES) {
        int d = col[e];
        int pos = atomicAdd(&g_cursor[d], 1);
        g_csr[pos] = row[e];
    }
}

// ---------------- gather aggregation: one warp per destination node ----------------
__global__ void k_gather(const float* __restrict__ x) {
    int gw = (blockIdx.x * blockDim.x + threadIdx.x) >> 5;
    int lane = threadIdx.x & 31;
    if (gw >= N_NODES) return;
    const int i = gw;
    const float di = g_dinv[i];
    const float4* x4 = (const float4*)x;

    float4 xi = x4[(size_t)i * 32 + lane];
    float w = di * di;                       // self-loop norm
    float4 acc;
    acc.x = w * xi.x; acc.y = w * xi.y; acc.z = w * xi.z; acc.w = w * xi.w;

    int s0 = g_offs[i], s1 = g_offs[i + 1];
    for (int j = s0; j < s1; j++) {
        int s = g_csr[j];
        float ws = di * g_dinv[s];
        float4 xs = x4[(size_t)s * 32 + lane];
        acc.x += ws * xs.x; acc.y += ws * xs.y; acc.z += ws * xs.z; acc.w += ws * xs.w;
    }
    ((float4*)g_agg)[(size_t)i * 32 + lane] = acc;
}

// ---------------- pool init ----------------
__global__ void k_pool_init() {
    int i = blockIdx.x * blockDim.x + threadIdx.x;
    if (i < 2 * NB * DIM) g_pool[i] = -FLT_MAX;
}

// ---------------- GEMM (agg @ W + b) + lrelu + segment_max epilogue ----------------
// 128x128 tile, BK=32, 256 threads, 8x8 micro-tile.
__global__ void k_gemm_pool(const float* __restrict__ W, const float* __restrict__ bias,
                            const int* __restrict__ batch, int branch) {
    __shared__ float As[128][33];
    __shared__ float Ws[32][128];
    const int tx = threadIdx.x & 15;
    const int ty = threadIdx.x >> 4;
    const int row0 = blockIdx.x * 128;

    float acc[8][8];
    #pragma unroll
    for (int i = 0; i < 8; i++)
        #pragma unroll
        for (int j = 0; j < 8; j++) acc[i][j] = 0.f;

    for (int kb = 0; kb < 4; kb++) {
        // load A tile: 128 rows x 32 cols (float4 coalesced)
        #pragma unroll
        for (int it = 0; it < 4; it++) {
            int flat = threadIdx.x + it * 256;   // float4 index, 1024 total
            int r = flat >> 3, c4 = (flat & 7) * 4;
            int gm = row0 + r;
            float4 v = make_float4(0.f, 0.f, 0.f, 0.f);
            if (gm < N_NODES)
                v = *(const float4*)&g_agg[(size_t)gm * 128 + kb * 32 + c4];
            As[r][c4 + 0] = v.x; As[r][c4 + 1] = v.y; As[r][c4 + 2] = v.z; As[r][c4 + 3] = v.w;
        }
        // load W tile: 32 rows x 128 cols
        #pragma unroll
        for (int it = 0; it < 4; it++) {
            int flat = threadIdx.x + it * 256;
            int r = flat >> 5, c4 = (flat & 31) * 4;
            *(float4*)&Ws[r][c4] = *(const float4*)&W[(size_t)(kb * 32 + r) * 128 + c4];
        }
        __syncthreads();
        #pragma unroll
        for (int k = 0; k < 32; k++) {
            float a[8], b[8];
            #pragma unroll
            for (int j = 0; j < 8; j++) a[j] = As[ty * 8 + j][k];
            #pragma unroll
            for (int j = 0; j < 8; j++) b[j] = Ws[k][tx * 8 + j];
            #pragma unroll
            for (int i = 0; i < 8; i++)
                #pragma unroll
                for (int j = 0; j < 8; j++) acc[i][j] += a[i] * b[j];
        }
        __syncthreads();
    }

    float* pool = &g_pool[branch * NB * DIM];
    #pragma unroll
    for (int i = 0; i < 8; i++) {
        int gm = row0 + ty * 8 + i;
        if (gm >= N_NODES) continue;
        int bt = batch[gm];
        float* pr = &pool[bt * DIM];
        #pragma unroll
        for (int j = 0; j < 8; j++) {
            int col = tx * 8 + j;
            float v = lrelu(acc[i][j] + bias[col]);
            atomicMaxFloat(&pr[col], v);
        }
    }
}

// ---------------- tail MLPs (tiny) ----------------
__global__ void k_fcp(const float* __restrict__ W1, const float* __restrict__ b1,
                      const float* __restrict__ W2, const float* __restrict__ b2) {
    int p = blockIdx.y, r = blockIdx.x, d = threadIdx.x;  // 128 threads
    __shared__ float prow[128];
    prow[d] = g_pool[p * NB * DIM + r * 128 + d];
    __syncthreads();
    const float* W = p ? W2 : W1;
    const float* bb = p ? b2 : b1;
    float s = bb[d];
    #pragma unroll 8
    for (int k = 0; k < 128; k++) s += prow[k] * W[k * 128 + d];
    g_gp[p * NB * DIM + r * 128 + d] = lrelu(s);
}

__global__ void k_fc1(const float* __restrict__ W, const float* __restrict__ b) {
    int r = blockIdx.x, d = threadIdx.x;   // 256 threads
    __shared__ float in[256];
    in[d] = (d < 128) ? g_gp[r * 128 + d] : g_gp[NB * DIM + r * 128 + (d - 128)];
    __syncthreads();
    float s = b[d];
    #pragma unroll 8
    for (int k = 0; k < 256; k++) s += in[k] * W[k * 256 + d];
    g_c1[r * 256 + d] = lrelu(s);
}

__global__ void k_fc2(const float* __restrict__ W, const float* __restrict__ b) {
    int r = blockIdx.x, d = threadIdx.x;   // 64 threads
    __shared__ float in[256];
    for (int k = d; k < 256; k += 64) in[k] = g_c1[r * 256 + k];
    __syncthreads();
    float s = b[d];
    #pragma unroll 8
    for (int k = 0; k < 256; k++) s += in[k] * W[k * 64 + d];
    g_c2[r * 64 + d] = lrelu(s);
}

__global__ void k_out(const float* __restrict__ W, const float* __restrict__ b,
                      float* __restrict__ out) {
    int r = threadIdx.x;   // 128 threads, 1 block
    float s = b[0];
    #pragma unroll
    for (int k = 0; k < 64; k++) s += g_c2[r * 64 + k] * W[k];
    out[r] = 1.f / (1.f + expf(-s));
}

// ---------------- host launcher ----------------
extern "C" void kernel_launch(void* const* d_in, const int* in_sizes, int n_in,
                              void* d_out, int out_size) {
    // Resolve the order of the first 6 tensors (dict order vs signature order).
    int ix[2], ie[2], ib[2];
    if (in_sizes[1] == N_NODES * DIM) {
        // dict order: p1x, p2x, p1e, p2e, p1b, p2b
        ix[0] = 0; ix[1] = 1; ie[0] = 2; ie[1] = 3; ib[0] = 4; ib[1] = 5;
    } else {
        // signature order: p1x, p1e, p1b, p2x, p2e, p2b
        ix[0] = 0; ie[0] = 1; ib[0] = 2; ix[1] = 3; ie[1] = 4; ib[1] = 5;
    }
    const float* convW[2] = { (const float*)d_in[6], (const float*)d_in[8] };
    const float* convB[2] = { (const float*)d_in[7], (const float*)d_in[9] };
    const float* fcp1W = (const float*)d_in[10];
    const float* fcp1B = (const float*)d_in[11];
    const float* fcp2W = (const float*)d_in[12];
    const float* fcp2B = (const float*)d_in[13];
    const float* fc1W  = (const float*)d_in[14];
    const float* fc1B  = (const float*)d_in[15];
    const float* fc2W  = (const float*)d_in[16];
    const float* fc2B  = (const float*)d_in[17];
    const float* outW  = (const float*)d_in[18];
    const float* outB  = (const float*)d_in[19];

    k_pool_init<<<(2 * NB * DIM + 255) / 256, 256>>>();

    for (int p = 0; p < 2; p++) {
        const float* x     = (const float*)d_in[ix[p]];
        const int*   erow  = (const int*)d_in[ie[p]];
        const int*   ecol  = erow + N_EDGES;
        const int*   batch = (const int*)d_in[ib[p]];

        k_zero_deg<<<(N_NODES + 255) / 256, 256>>>();
        k_count<<<(N_EDGES + 255) / 256, 256>>>(ecol);
        k_dinv<<<(N_NODES + 255) / 256, 256>>>();
        k_scan1<<<98, 1024>>>();
        k_scan2<<<1, 128>>>();
        k_scan3<<<98, 1024>>>();
        k_fill<<<(N_EDGES + 255) / 256, 256>>>(erow, ecol);
        k_gather<<<(N_NODES * 32 + 255) / 256, 256>>>(x);
        k_gemm_pool<<<(N_NODES + 127) / 128, 256>>>(convW[p], convB[p], batch, p);
    }

    k_fcp<<<dim3(NB, 2), 128>>>(fcp1W, fcp1B, fcp2W, fcp2B);
    k_fc1<<<NB, 256>>>(fc1W, fc1B);
    k_fc2<<<NB, 64>>>(fc2W, fc2B);
    k_out<<<1, 128>>>(outW, outB, (float*)d_out);
}